// round 15
// baseline (speedup 1.0000x reference)
#include <cuda_runtime.h>
#include <cuda_fp16.h>
#include <cstdint>

#define BB 8192
#define TT 96
#define FF 64
#define HH 256

// ---------------- static device buffers ----------------
// Dense weights: [10 chunks][384 rows][64 k] fp16. chunk = pair*5+kc.
// row d = blk_l*48 + slot; j = pair*128 + blk_l*16 + (slot%16);
// slot/16: 0=z,1=r,2=hh(kc<4)/xh(kc==4). k = kc*64+kk (kc<4: Rw; kc==4: Kw[1+kk]).
// blk_l == wn: each wn warp-pair consumes rows [wn*48, wn*48+48).
__device__ __align__(256) __half g_W[10 * 384 * 64];
__device__ __align__(256) __half g_f16[(size_t)BB * TT * FF];  // features fp16
__device__ float g_epi[HH * 8];  // {k0z,k0r,k0h,bz,br,bxh,bhh,dw}

// ---------------- helpers ----------------
static __device__ __forceinline__ uint32_t smem_u32(const void* p) {
    uint32_t a;
    asm("{ .reg .u64 t; cvta.to.shared.u64 t, %1; cvt.u32.u64 %0, t; }"
        : "=r"(a) : "l"(p));
    return a;
}
static __device__ __forceinline__ void cpasync16(uint32_t dst, const void* src) {
    asm volatile("cp.async.cg.shared.global [%0], [%1], 16;"
                 :: "r"(dst), "l"(src) : "memory");
}
static __device__ __forceinline__ void ldm4(uint32_t* d, uint32_t a) {
    asm volatile("ldmatrix.sync.aligned.m8n8.x4.shared.b16 {%0,%1,%2,%3}, [%4];"
                 : "=r"(d[0]), "=r"(d[1]), "=r"(d[2]), "=r"(d[3]) : "r"(a));
}
static __device__ __forceinline__ void mmaf16(float* c, const uint32_t* a,
                                              uint32_t b0, uint32_t b1) {
    asm volatile(
        "mma.sync.aligned.m16n8k16.row.col.f32.f16.f16.f32 "
        "{%0,%1,%2,%3},{%4,%5,%6,%7},{%8,%9},{%0,%1,%2,%3};"
        : "+f"(c[0]), "+f"(c[1]), "+f"(c[2]), "+f"(c[3])
        : "r"(a[0]), "r"(a[1]), "r"(a[2]), "r"(a[3]), "r"(b0), "r"(b1));
}
static __device__ __forceinline__ float tanha(float x) {
    float y;
    asm("tanh.approx.f32 %0, %1;" : "=f"(y) : "f"(x));
    return y;
}
// sigmoid via MUFU.TANH: 1 MUFU instead of 2
__device__ __forceinline__ float sigf(float x) {
    return fmaf(tanha(0.5f * x), 0.5f, 0.5f);
}
// accurate tanh for the candidate (protects error budget)
__device__ __forceinline__ float tanhfast(float x) {
    return 1.0f - __fdividef(2.0f, __expf(2.0f * x) + 1.0f);
}

// ---------------- prep kernels ----------------
__global__ void prep_feat(const float* __restrict__ f) {
    size_t i = (size_t)blockIdx.x * 256 + threadIdx.x;
    if (i >= (size_t)BB * TT * FF) return;
    g_f16[i] = __float2half_rn(f[i]);
}

__global__ void prep_W(const float* __restrict__ Kw, const float* __restrict__ Rw) {
    int idx = blockIdx.x * 256 + threadIdx.x;
    if (idx >= 10 * 384 * 64) return;
    int kk = idx & 63;
    int d = (idx >> 6) % 384;
    int c10 = idx / (384 * 64);
    int pair = c10 / 5, kc = c10 % 5;
    int blk_l = d / 48, slot = d % 48;
    int gate = slot >> 4, jl = slot & 15;
    int j = pair * 128 + blk_l * 16 + jl;
    int off = (gate == 0) ? 0 : (gate == 1) ? 256 : 512;
    float v;
    if (kc < 4) v = Rw[(kc * 64 + kk) * 768 + off + j];
    else        v = Kw[(1 + kk) * 768 + off + j];
    g_W[idx] = __float2half_rn(v);
}

__global__ void prep_epi(const float* __restrict__ Kw, const float* __restrict__ ib,
                         const float* __restrict__ rb, const float* __restrict__ dw) {
    int j = threadIdx.x;
    float* e = &g_epi[j * 8];
    e[0] = Kw[j];
    e[1] = Kw[256 + j];
    e[2] = Kw[512 + j];
    e[3] = ib[j] + rb[j];
    e[4] = ib[256 + j] + rb[256 + j];
    e[5] = ib[512 + j];
    e[6] = rb[512 + j];
    e[7] = dw[j];
}

// ---------------- persistent scan kernel ----------------
// SMEM: ring 2 slots x [8 wn-pairs x 6KB] = 96K | Apanels 2x5x8K | epi 8K
//       | prev 2x64f | dacc 64f        (lo plane removed: h state lives in regs)
#define RING_OFF 0
#define APAN_OFF 98304
#define EPI_OFF  180224
#define PREV_OFF 188416
#define DACC_OFF 188928
#define SMEM_TOTAL 189184

// Fused epilogue for one j-pair, PR = compile-time pair index so hreg stays
// register-indexed. hold comes from hreg (exact fp32 state); only the fp16-hi
// panel (parity p^1) is written for the next step's GEMM operand.
template <int PR>
static __device__ __forceinline__ void epilogue(
    char* sm, float (&hreg)[32], float (&acc)[2][6][4], float (&accx)[2][2][4],
    const float* s_epi, const float* s_prev, float* s_dacc,
    int p, int wm, int wn, int tq, int tr) {
    const int jbase = PR * 128 + wn * 16;
    const uint32_t hwr = APAN_OFF + (uint32_t)(p ^ 1) * 40960u;  // byte offset
    float dacc[2][2] = {{0.f, 0.f}, {0.f, 0.f}};

#pragma unroll
    for (int o = 0; o < 2; o++) {
        const int j0 = jbase + o * 8 + 2 * tq;
        // epilogue constants for this o (reused across mi,rs)
        float ev[2][8];
#pragma unroll
        for (int i = 0; i < 2; i++) {
            const float* e = &s_epi[(j0 + i) * 8];
            float4 u0 = *(const float4*)e;
            float4 u1 = *(const float4*)(e + 4);
            ev[i][0] = u0.x; ev[i][1] = u0.y; ev[i][2] = u0.z; ev[i][3] = u0.w;
            ev[i][4] = u1.x; ev[i][5] = u1.y; ev[i][6] = u1.z; ev[i][7] = u1.w;
        }
        const int cc = (j0 & 63) >> 3;
#pragma unroll
        for (int mi = 0; mi < 2; mi++)
#pragma unroll
            for (int rs = 0; rs < 2; rs++) {
                const int m = wm * 32 + mi * 16 + rs * 8 + tr;
                const float prev = s_prev[p * 64 + m];
                float hn2[2];
#pragma unroll
                for (int i = 0; i < 2; i++) {
                    const float* e = ev[i];
                    float cz = acc[mi][0 + o][rs * 2 + i] + prev * e[0] + e[3];
                    float cr = acc[mi][2 + o][rs * 2 + i] + prev * e[1] + e[4];
                    float cx = accx[mi][o][rs * 2 + i] + prev * e[2] + e[5];
                    float ch = acc[mi][4 + o][rs * 2 + i] + e[6];
                    float z = sigf(cz), r = sigf(cr);
                    float cand = tanhfast(cx + r * ch);
                    float hold = hreg[PR * 16 + mi * 8 + rs * 4 + o * 2 + i];
                    float hn = z * hold + (1.f - z) * cand;
                    hreg[PR * 16 + mi * 8 + rs * 4 + o * 2 + i] = hn;
                    dacc[mi][rs] += hn * e[7];
                    hn2[i] = hn;
                }
                __half h0 = __float2half_rn(hn2[0]);
                __half h1 = __float2half_rn(hn2[1]);
                const uint32_t hoff = (uint32_t)((j0 >> 6) * 8192 + m * 128 +
                                      ((cc ^ (m & 7)) << 4) + (j0 & 7) * 2);
                *(uint32_t*)(sm + hwr + hoff) =
                    (uint32_t)__half_as_ushort(h0) |
                    ((uint32_t)__half_as_ushort(h1) << 16);
            }
    }
#pragma unroll
    for (int mi = 0; mi < 2; mi++)
#pragma unroll
        for (int rs = 0; rs < 2; rs++) {
            float d = dacc[mi][rs];
            d += __shfl_xor_sync(0xffffffffu, d, 1);
            d += __shfl_xor_sync(0xffffffffu, d, 2);
            if (tq == 0)
                atomicAdd(&s_dacc[wm * 32 + mi * 16 + rs * 8 + tr], d);
        }
}

__global__ __launch_bounds__(512, 1) void scan_kernel(
    const float* __restrict__ hs0, const float* __restrict__ inp0,
    const float* __restrict__ db, float* __restrict__ out) {
    extern __shared__ char sm[];
    const uint32_t smb = smem_u32(sm);
    float* s_epi = (float*)(sm + EPI_OFF);
    float* s_prev = (float*)(sm + PREV_OFF);   // [2][64]
    float* s_dacc = (float*)(sm + DACC_OFF);   // [64]

    const int tid = threadIdx.x, lane = tid & 31, wid = tid >> 5;
    const int b0 = blockIdx.x * 64;
    const int wm = wid >> 3, wn = wid & 7;     // 2m x 8n warps; warp = 32m x 48n
    const int tq = lane & 3, tr = lane >> 2;

    const int arow = wm * 32 + (lane & 15), asel = lane >> 4;
    const int bsub = lane >> 3, bl8 = lane & 7;
    const int brow0 = ((bsub >> 1) << 3) + bl8, bsel = bsub & 1;  // LOCAL to pair tile

    // ---- per-pair weight loader; feat(t+1) piggybacks on chunk c%10==8 ----
    auto issue = [&](int c) {
        if (c >= TT * 10) return;
        const int cm = c % 10;
        const uint32_t pbase = smb + RING_OFF + (uint32_t)(c & 1) * 49152u + wn * 6144u;
        const __half* wsrc = &g_W[cm * (384 * 64) + wn * 48 * 64];
#pragma unroll
        for (int i = 0; i < 6; i++) {
            int u = lane + i * 32;
            int r = wm * 24 + (u >> 3), cc = u & 7;
            cpasync16(pbase + r * 128 + ((cc ^ (r & 7)) << 4), wsrc + r * 64 + cc * 8);
        }
        if (cm == 8) {
            int tn = c / 10 + 1;
            if (tn < TT) {
                int r = tid >> 3, cc = tid & 7;
                uint32_t fb = smb + APAN_OFF + (uint32_t)(tn & 1) * 40960u + 4u * 8192u;
                cpasync16(fb + r * 128 + ((cc ^ (r & 7)) << 4),
                          &g_f16[((size_t)(b0 + r) * TT + tn) * FF + cc * 8]);
            }
        }
        asm volatile("cp.async.commit_group;" ::: "memory");
    };

    issue(0);

    // ---- init: h -> panel[0] (fp16 hi) ; hreg (exact fp32) ; feat(0) ; epi ; prev ----
    for (int idx = tid; idx < 64 * 256; idx += 512) {
        int m = idx >> 8, j = idx & 255;
        float v = hs0[(size_t)(b0 + m) * HH + j];
        int cc = (j & 63) >> 3;
        *(__half*)(sm + APAN_OFF + (j >> 6) * 8192 + m * 128 +
                   ((cc ^ (m & 7)) << 4) + (j & 7) * 2) = __float2half_rn(v);
    }
    float hreg[32];
#pragma unroll
    for (int pr = 0; pr < 2; pr++)
#pragma unroll
        for (int mi = 0; mi < 2; mi++)
#pragma unroll
            for (int rs = 0; rs < 2; rs++)
#pragma unroll
                for (int o = 0; o < 2; o++)
#pragma unroll
                    for (int i = 0; i < 2; i++) {
                        int m = wm * 32 + mi * 16 + rs * 8 + tr;
                        int j = pr * 128 + wn * 16 + o * 8 + 2 * tq + i;
                        hreg[pr * 16 + mi * 8 + rs * 4 + o * 2 + i] =
                            hs0[(size_t)(b0 + m) * HH + j];
                    }
    {   // feat t=0
        int r = tid >> 3, cc = tid & 7;
        *(uint4*)(sm + APAN_OFF + 4 * 8192 + r * 128 + ((cc ^ (r & 7)) << 4)) =
            *(const uint4*)&g_f16[((size_t)(b0 + r) * TT) * FF + cc * 8];
    }
    for (int i = tid; i < 2048; i += 512) s_epi[i] = g_epi[i];
    if (tid < 64) {
        s_prev[tid] = inp0[b0 + tid];
        s_dacc[tid] = 0.f;
    }
    __syncthreads();

    float acc[2][6][4], accx[2][2][4];
#pragma unroll
    for (int mi = 0; mi < 2; mi++) {
#pragma unroll
        for (int a = 0; a < 6; a++)
#pragma unroll
            for (int q = 0; q < 4; q++) acc[mi][a][q] = 0.f;
#pragma unroll
        for (int a = 0; a < 2; a++)
#pragma unroll
            for (int q = 0; q < 4; q++) accx[mi][a][q] = 0.f;
    }

#pragma unroll 1
    for (int c = 0; c < TT * 10; ++c) {
        // Drain own group; 64-thread pair barrier publishes the pair's B tile
        // and proves slot (c+1)&1 is recyclable.
        asm volatile("cp.async.wait_group 0;" ::: "memory");
        asm volatile("bar.sync %0, 64;" :: "r"(1 + wn) : "memory");
        issue(c + 1);

        const int t = c / 10, cm = c % 10, pair = cm / 5, kc = cm % 5;
        const int p = t & 1;
        const uint32_t bbase = smb + RING_OFF + (uint32_t)(c & 1) * 49152u + wn * 6144u;
        const uint32_t abase = smb + APAN_OFF + (uint32_t)p * 40960u + kc * 8192u;
        const bool isx = (kc == 4);

#pragma unroll
        for (int q = 0; q < 4; q++) {
            uint32_t afr[2][4];
#pragma unroll
            for (int mi = 0; mi < 2; mi++) {
                int r = arow + mi * 16, cc = q * 2 + asel;
                ldm4(afr[mi], abase + r * 128 + ((cc ^ (r & 7)) << 4));
            }
#pragma unroll
            for (int pp = 0; pp < 3; pp++) {
                int r = brow0 + pp * 16, cc = q * 2 + bsel;
                uint32_t v[4];
                ldm4(v, bbase + r * 128 + ((cc ^ (r & 7)) << 4));
                if (pp < 2 || !isx) {
#pragma unroll
                    for (int mi = 0; mi < 2; mi++) {
                        mmaf16(acc[mi][2 * pp], afr[mi], v[0], v[1]);
                        mmaf16(acc[mi][2 * pp + 1], afr[mi], v[2], v[3]);
                    }
                } else {
#pragma unroll
                    for (int mi = 0; mi < 2; mi++) {
                        mmaf16(accx[mi][0], afr[mi], v[0], v[1]);
                        mmaf16(accx[mi][1], afr[mi], v[2], v[3]);
                    }
                }
            }
        }

        if (isx) {
            if (pair == 0)
                epilogue<0>(sm, hreg, acc, accx, s_epi, s_prev, s_dacc,
                            p, wm, wn, tq, tr);
            else
                epilogue<1>(sm, hreg, acc, accx, s_epi, s_prev, s_dacc,
                            p, wm, wn, tq, tr);
            // reset accumulators for the next pair
#pragma unroll
            for (int mi = 0; mi < 2; mi++) {
#pragma unroll
                for (int a = 0; a < 6; a++)
#pragma unroll
                    for (int q = 0; q < 4; q++) acc[mi][a][q] = 0.f;
#pragma unroll
                for (int a = 0; a < 2; a++)
#pragma unroll
                    for (int q = 0; q < 4; q++) accx[mi][a][q] = 0.f;
            }
        }

        if (cm == 9) {
            // CTA barrier #1: all epilogue writes + dacc atomics done.
            __syncthreads();
            if (tid < 64) {
                float v = s_dacc[tid] + db[0];
                s_prev[((t + 1) & 1) * 64 + tid] = v;
                out[(size_t)(b0 + tid) * TT + t] = v;
                s_dacc[tid] = 0.f;
            }
            // CTA barrier #2: publish prev/dacc before step t+1 consumes them.
            __syncthreads();
        }
    }
}

// ---------------- launch ----------------
extern "C" void kernel_launch(void* const* d_in, const int* in_sizes, int n_in,
                              void* d_out, int out_size) {
    const float* feat  = (const float*)d_in[0];
    const float* hs0   = (const float*)d_in[1];
    const float* inp0  = (const float*)d_in[2];
    const float* Kw    = (const float*)d_in[3];
    const float* Rw    = (const float*)d_in[4];
    const float* ibias = (const float*)d_in[5];
    const float* rbias = (const float*)d_in[6];
    const float* dw    = (const float*)d_in[7];
    const float* db    = (const float*)d_in[8];
    float* out = (float*)d_out;

    cudaFuncSetAttribute(scan_kernel, cudaFuncAttributeMaxDynamicSharedMemorySize,
                         SMEM_TOTAL);

    size_t nf = (size_t)BB * TT * FF;
    prep_feat<<<(unsigned)((nf + 255) / 256), 256>>>(feat);
    prep_W<<<(10 * 384 * 64 + 255) / 256, 256>>>(Kw, Rw);
    prep_epi<<<1, 256>>>(Kw, ibias, rbias, dw);

    scan_kernel<<<128, 512, SMEM_TOTAL>>>(hs0, inp0, db, out);
}

// round 16
// speedup vs baseline: 1.0825x; 1.0825x over previous
#include <cuda_runtime.h>
#include <cuda_fp16.h>
#include <cstdint>

#define BB 8192
#define TT 96
#define FF 64
#define HH 256

// ---------------- static device buffers ----------------
// Dense weights: [10 chunks][384 rows][64 k] fp16. chunk = pair*5+kc.
// row d = blk_l*48 + slot; j = pair*128 + blk_l*16 + (slot%16);
// slot/16: 0=z,1=r,2=hh(kc<4)/xh(kc==4). k = kc*64+kk (kc<4: Rw; kc==4: Kw[1+kk]).
// blk_l == wn: each wn warp-pair consumes rows [wn*48, wn*48+48).
__device__ __align__(256) __half g_W[10 * 384 * 64];
__device__ __align__(256) __half g_f16[(size_t)BB * TT * FF];  // features fp16
__device__ float g_epi[HH * 8];  // {k0z,k0r,k0h,bz,br,bxh,bhh,dw}

// ---------------- helpers ----------------
static __device__ __forceinline__ uint32_t smem_u32(const void* p) {
    uint32_t a;
    asm("{ .reg .u64 t; cvta.to.shared.u64 t, %1; cvt.u32.u64 %0, t; }"
        : "=r"(a) : "l"(p));
    return a;
}
static __device__ __forceinline__ void cpasync16(uint32_t dst, const void* src) {
    asm volatile("cp.async.cg.shared.global [%0], [%1], 16;"
                 :: "r"(dst), "l"(src) : "memory");
}
static __device__ __forceinline__ void ldm4(uint32_t* d, uint32_t a) {
    asm volatile("ldmatrix.sync.aligned.m8n8.x4.shared.b16 {%0,%1,%2,%3}, [%4];"
                 : "=r"(d[0]), "=r"(d[1]), "=r"(d[2]), "=r"(d[3]) : "r"(a));
}
static __device__ __forceinline__ void mmaf16(float* c, const uint32_t* a,
                                              uint32_t b0, uint32_t b1) {
    asm volatile(
        "mma.sync.aligned.m16n8k16.row.col.f32.f16.f16.f32 "
        "{%0,%1,%2,%3},{%4,%5,%6,%7},{%8,%9},{%0,%1,%2,%3};"
        : "+f"(c[0]), "+f"(c[1]), "+f"(c[2]), "+f"(c[3])
        : "r"(a[0]), "r"(a[1]), "r"(a[2]), "r"(a[3]), "r"(b0), "r"(b1));
}
static __device__ __forceinline__ float tanha(float x) {
    float y;
    asm("tanh.approx.f32 %0, %1;" : "=f"(y) : "f"(x));
    return y;
}
// sigmoid via MUFU.TANH: 1 MUFU instead of 2
__device__ __forceinline__ float sigf(float x) {
    return fmaf(tanha(0.5f * x), 0.5f, 0.5f);
}
// accurate tanh for the candidate (protects error budget)
__device__ __forceinline__ float tanhfast(float x) {
    return 1.0f - __fdividef(2.0f, __expf(2.0f * x) + 1.0f);
}
__device__ __forceinline__ float hfpart(uint32_t w, int hi) {
    __half_raw r;
    r.x = hi ? (unsigned short)(w >> 16) : (unsigned short)(w & 0xffff);
    return __half2float(__half(r));
}

// ---------------- prep kernels ----------------
__global__ void prep_feat(const float* __restrict__ f) {
    size_t i = (size_t)blockIdx.x * 256 + threadIdx.x;
    if (i >= (size_t)BB * TT * FF) return;
    g_f16[i] = __float2half_rn(f[i]);
}

__global__ void prep_W(const float* __restrict__ Kw, const float* __restrict__ Rw) {
    int idx = blockIdx.x * 256 + threadIdx.x;
    if (idx >= 10 * 384 * 64) return;
    int kk = idx & 63;
    int d = (idx >> 6) % 384;
    int c10 = idx / (384 * 64);
    int pair = c10 / 5, kc = c10 % 5;
    int blk_l = d / 48, slot = d % 48;
    int gate = slot >> 4, jl = slot & 15;
    int j = pair * 128 + blk_l * 16 + jl;
    int off = (gate == 0) ? 0 : (gate == 1) ? 256 : 512;
    float v;
    if (kc < 4) v = Rw[(kc * 64 + kk) * 768 + off + j];
    else        v = Kw[(1 + kk) * 768 + off + j];
    g_W[idx] = __float2half_rn(v);
}

__global__ void prep_epi(const float* __restrict__ Kw, const float* __restrict__ ib,
                         const float* __restrict__ rb, const float* __restrict__ dw) {
    int j = threadIdx.x;
    float* e = &g_epi[j * 8];
    e[0] = Kw[j];
    e[1] = Kw[256 + j];
    e[2] = Kw[512 + j];
    e[3] = ib[j] + rb[j];
    e[4] = ib[256 + j] + rb[256 + j];
    e[5] = ib[512 + j];
    e[6] = rb[512 + j];
    e[7] = dw[j];
}

// ---------------- persistent scan kernel ----------------
// SMEM: ring 2 slots x [8 wn-pairs x 6KB] = 96K | Apanels 2x5x8K | h_lo 64x264 halfs
//       | epi 8K | prev 2x64f | dacc 64f
#define RING_OFF 0
#define APAN_OFF 98304
#define LO_OFF   180224
#define LOSTRIDE 264
#define EPI_OFF  214016
#define PREV_OFF 222208
#define DACC_OFF 222720
#define SMEM_TOTAL 222976

__global__ __launch_bounds__(512, 1) void scan_kernel(
    const float* __restrict__ hs0, const float* __restrict__ inp0,
    const float* __restrict__ db, float* __restrict__ out) {
    extern __shared__ char sm[];
    const uint32_t smb = smem_u32(sm);
    float* s_epi = (float*)(sm + EPI_OFF);
    float* s_prev = (float*)(sm + PREV_OFF);   // [2][64]
    float* s_dacc = (float*)(sm + DACC_OFF);   // [64]
    __half* s_lo = (__half*)(sm + LO_OFF);     // [64][LOSTRIDE]

    const int tid = threadIdx.x, lane = tid & 31, wid = tid >> 5;
    const int b0 = blockIdx.x * 64;
    const int wm = wid >> 3, wn = wid & 7;     // 2m x 8n warps; warp = 32m x 48n
    const int tq = lane & 3, tr = lane >> 2;

    const int arow = wm * 32 + (lane & 15), asel = lane >> 4;
    const int bsub = lane >> 3, bl8 = lane & 7;
    const int brow0 = ((bsub >> 1) << 3) + bl8, bsel = bsub & 1;  // LOCAL to pair tile

    // ---- precomputed invariant swizzle+row tables (q -> byte offset) ----
    uint32_t aswz[4], bswz[4];
#pragma unroll
    for (int q = 0; q < 4; q++) {
        aswz[q] = (uint32_t)(arow * 128) + (uint32_t)((((q * 2 + asel) ^ (arow & 7)) << 4));
        bswz[q] = (uint32_t)(brow0 * 128) + (uint32_t)((((q * 2 + bsel) ^ (brow0 & 7)) << 4));
    }

    // ---- weight-loader invariants: one src pointer (stepped per chunk) and
    //      precomputed dst bases per ring slot; i advances rows by 4. ----
    const int lr0 = wm * 24 + (lane >> 3);
    const int lcc = lane & 7;
    const __half* wptr = g_W + (size_t)wn * 48 * 64 + (size_t)lr0 * 64 + lcc * 8;
    const uint32_t swzA = (uint32_t)((lcc ^ (lr0 & 7)) << 4);
    const uint32_t swzB = (uint32_t)((lcc ^ ((lr0 + 4) & 7)) << 4);
    const uint32_t pb0 = smb + RING_OFF + wn * 6144u;
    const uint32_t d0_0 = pb0 + (uint32_t)lr0 * 128 + swzA;
    const uint32_t d1_0 = pb0 + (uint32_t)(lr0 + 4) * 128 + swzB;
    const uint32_t d0_1 = d0_0 + 49152u, d1_1 = d1_0 + 49152u;

    // ---- per-pair weight loader; feat(t+1) piggybacks on chunk c%10==8 ----
    auto issue = [&](int c) {
        if (c >= TT * 10) return;
        const int cm = c % 10;
        const int s = c & 1;
        const uint32_t dd0 = s ? d0_1 : d0_0;
        const uint32_t dd1 = s ? d1_1 : d1_0;
#pragma unroll
        for (int i = 0; i < 6; i++) {
            uint32_t dst = ((i & 1) ? dd1 : dd0) + (uint32_t)(i >> 1) * 1024u;
            cpasync16(dst, wptr + i * 256);   // +4 rows = +256 halfs per i
        }
        if (cm == 8) {
            int tn = c / 10 + 1;
            if (tn < TT) {
                int r = tid >> 3, cc = tid & 7;
                uint32_t fb = smb + APAN_OFF + (uint32_t)(tn & 1) * 40960u + 4u * 8192u;
                cpasync16(fb + r * 128 + ((cc ^ (r & 7)) << 4),
                          &g_f16[((size_t)(b0 + r) * TT + tn) * FF + cc * 8]);
            }
        }
        asm volatile("cp.async.commit_group;" ::: "memory");
        wptr += 384 * 64;
        if (cm == 9) wptr -= 10 * 384 * 64;
    };

    issue(0);

    // ---- init: h -> panels[0] + lo ; feat(0) ; epi ; prev ----
    for (int idx = tid; idx < 64 * 256; idx += 512) {
        int m = idx >> 8, j = idx & 255;
        float v = hs0[(size_t)(b0 + m) * HH + j];
        __half hi = __float2half_rn(v);
        s_lo[m * LOSTRIDE + j] = __float2half_rn(v - __half2float(hi));
        int cc = (j & 63) >> 3;
        *(__half*)(sm + APAN_OFF + (j >> 6) * 8192 + m * 128 +
                   ((cc ^ (m & 7)) << 4) + (j & 7) * 2) = hi;
    }
    {   // feat t=0
        int r = tid >> 3, cc = tid & 7;
        *(uint4*)(sm + APAN_OFF + 4 * 8192 + r * 128 + ((cc ^ (r & 7)) << 4)) =
            *(const uint4*)&g_f16[((size_t)(b0 + r) * TT) * FF + cc * 8];
    }
    for (int i = tid; i < 2048; i += 512) s_epi[i] = g_epi[i];
    if (tid < 64) {
        s_prev[tid] = inp0[b0 + tid];
        s_dacc[tid] = 0.f;
    }
    __syncthreads();

    float acc[2][6][4], accx[2][2][4];
#pragma unroll
    for (int mi = 0; mi < 2; mi++) {
#pragma unroll
        for (int a = 0; a < 6; a++)
#pragma unroll
            for (int q = 0; q < 4; q++) acc[mi][a][q] = 0.f;
#pragma unroll
        for (int a = 0; a < 2; a++)
#pragma unroll
            for (int q = 0; q < 4; q++) accx[mi][a][q] = 0.f;
    }

#pragma unroll 1
    for (int c = 0; c < TT * 10; ++c) {
        // Drain own group; 64-thread pair barrier publishes the pair's B tile
        // and proves slot (c+1)&1 is recyclable.
        asm volatile("cp.async.wait_group 0;" ::: "memory");
        asm volatile("bar.sync %0, 64;" :: "r"(1 + wn) : "memory");
        issue(c + 1);

        const int t = c / 10, cm = c % 10, pair = cm / 5, kc = cm % 5;
        const int p = t & 1;
        const uint32_t bb0 = smb + RING_OFF + (uint32_t)(c & 1) * 49152u + wn * 6144u;
        const uint32_t ab0 = smb + APAN_OFF + (uint32_t)p * 40960u + kc * 8192u;
        const bool isx = (kc == 4);

#pragma unroll
        for (int q = 0; q < 4; q++) {
            uint32_t afr[2][4];
#pragma unroll
            for (int mi = 0; mi < 2; mi++)
                ldm4(afr[mi], ab0 + (uint32_t)mi * 2048u + aswz[q]);
#pragma unroll
            for (int pp = 0; pp < 3; pp++) {
                uint32_t v[4];
                ldm4(v, bb0 + (uint32_t)pp * 2048u + bswz[q]);
                if (pp < 2 || !isx) {
#pragma unroll
                    for (int mi = 0; mi < 2; mi++) {
                        mmaf16(acc[mi][2 * pp], afr[mi], v[0], v[1]);
                        mmaf16(acc[mi][2 * pp + 1], afr[mi], v[2], v[3]);
                    }
                } else {
#pragma unroll
                    for (int mi = 0; mi < 2; mi++) {
                        mmaf16(accx[mi][0], afr[mi], v[0], v[1]);
                        mmaf16(accx[mi][1], afr[mi], v[2], v[3]);
                    }
                }
            }
        }

        if (isx) {
            // ---- fused epilogue for this pair ----
            const int jbase = pair * 128 + wn * 16;
            const uint32_t hrd = APAN_OFF + (uint32_t)p * 40960u;        // byte offs
            const uint32_t hwr = APAN_OFF + (uint32_t)(p ^ 1) * 40960u;  // byte offs

            // hoisted per-o constants: epilogue coeffs + swizzle bases
            float ev[2][2][8];
            uint32_t swzo[2];
            int j0o[2];
#pragma unroll
            for (int o = 0; o < 2; o++) {
                const int j0 = jbase + o * 8 + 2 * tq;
                j0o[o] = j0;
                const int cc = (j0 & 63) >> 3;
                swzo[o] = (uint32_t)((j0 >> 6) * 8192 + ((cc ^ tr) << 4) + (j0 & 7) * 2);
#pragma unroll
                for (int i = 0; i < 2; i++) {
                    const float* e = &s_epi[(j0 + i) * 8];
                    float4 u0 = *(const float4*)e;
                    float4 u1 = *(const float4*)(e + 4);
                    ev[o][i][0] = u0.x; ev[o][i][1] = u0.y;
                    ev[o][i][2] = u0.z; ev[o][i][3] = u0.w;
                    ev[o][i][4] = u1.x; ev[o][i][5] = u1.y;
                    ev[o][i][6] = u1.z; ev[o][i][7] = u1.w;
                }
            }

#pragma unroll
            for (int mi = 0; mi < 2; mi++)
#pragma unroll
                for (int rs = 0; rs < 2; rs++) {
                    const int m = wm * 32 + mi * 16 + rs * 8 + tr;
                    const uint32_t m128 = (uint32_t)m * 128u;
                    const float prev = s_prev[p * 64 + m];
                    float dacc = 0.f;
#pragma unroll
                    for (int o = 0; o < 2; o++) {
                        const int j0 = j0o[o];
                        const uint32_t hoff = swzo[o] + m128;
                        uint32_t hw = *(const uint32_t*)(sm + hrd + hoff);
                        uint32_t lw = *(const uint32_t*)&s_lo[m * LOSTRIDE + j0];
                        float hn2[2];
#pragma unroll
                        for (int i = 0; i < 2; i++) {
                            const float* e = ev[o][i];
                            float cz = acc[mi][0 + o][rs * 2 + i] + prev * e[0] + e[3];
                            float cr = acc[mi][2 + o][rs * 2 + i] + prev * e[1] + e[4];
                            float cx = accx[mi][o][rs * 2 + i] + prev * e[2] + e[5];
                            float ch = acc[mi][4 + o][rs * 2 + i] + e[6];
                            float z = sigf(cz), r = sigf(cr);
                            float cand = tanhfast(cx + r * ch);
                            float hold = hfpart(hw, i) + hfpart(lw, i);
                            float hn = z * hold + (1.f - z) * cand;
                            dacc += hn * e[7];
                            hn2[i] = hn;
                        }
                        __half h0 = __float2half_rn(hn2[0]);
                        __half h1 = __float2half_rn(hn2[1]);
                        __half l0 = __float2half_rn(hn2[0] - __half2float(h0));
                        __half l1 = __float2half_rn(hn2[1] - __half2float(h1));
                        *(uint32_t*)(sm + hwr + hoff) =
                            (uint32_t)__half_as_ushort(h0) |
                            ((uint32_t)__half_as_ushort(h1) << 16);
                        *(uint32_t*)&s_lo[m * LOSTRIDE + j0] =
                            (uint32_t)__half_as_ushort(l0) |
                            ((uint32_t)__half_as_ushort(l1) << 16);
                    }
                    dacc += __shfl_xor_sync(0xffffffffu, dacc, 1);
                    dacc += __shfl_xor_sync(0xffffffffu, dacc, 2);
                    if (tq == 0) atomicAdd(&s_dacc[m], dacc);
                }
            // reset accumulators for the next pair
#pragma unroll
            for (int mi = 0; mi < 2; mi++) {
#pragma unroll
                for (int a = 0; a < 6; a++)
#pragma unroll
                    for (int q = 0; q < 4; q++) acc[mi][a][q] = 0.f;
#pragma unroll
                for (int a = 0; a < 2; a++)
#pragma unroll
                    for (int q = 0; q < 4; q++) accx[mi][a][q] = 0.f;
            }
        }

        if (cm == 9) {
            // CTA barrier #1: all epilogue writes + dacc atomics done.
            __syncthreads();
            if (tid < 64) {
                float v = s_dacc[tid] + db[0];
                s_prev[((t + 1) & 1) * 64 + tid] = v;
                out[(size_t)(b0 + tid) * TT + t] = v;
                s_dacc[tid] = 0.f;
            }
            // CTA barrier #2: publish prev/dacc before step t+1 consumes them.
            __syncthreads();
        }
    }
}

// ---------------- launch ----------------
extern "C" void kernel_launch(void* const* d_in, const int* in_sizes, int n_in,
                              void* d_out, int out_size) {
    const float* feat  = (const float*)d_in[0];
    const float* hs0   = (const float*)d_in[1];
    const float* inp0  = (const float*)d_in[2];
    const float* Kw    = (const float*)d_in[3];
    const float* Rw    = (const float*)d_in[4];
    const float* ibias = (const float*)d_in[5];
    const float* rbias = (const float*)d_in[6];
    const float* dw    = (const float*)d_in[7];
    const float* db    = (const float*)d_in[8];
    float* out = (float*)d_out;

    cudaFuncSetAttribute(scan_kernel, cudaFuncAttributeMaxDynamicSharedMemorySize,
                         SMEM_TOTAL);

    size_t nf = (size_t)BB * TT * FF;
    prep_feat<<<(unsigned)((nf + 255) / 256), 256>>>(feat);
    prep_W<<<(10 * 384 * 64 + 255) / 256, 256>>>(Kw, Rw);
    prep_epi<<<1, 256>>>(Kw, ibias, rbias, dw);

    scan_kernel<<<128, 512, SMEM_TOTAL>>>(hs0, inp0, db, out);
}

// round 17
// speedup vs baseline: 1.0907x; 1.0076x over previous
#include <cuda_runtime.h>
#include <cuda_fp16.h>
#include <cstdint>

#define BB 8192
#define TT 96
#define FF 64
#define HH 256

// ---------------- static device buffers ----------------
// Dense weights: [10 chunks][384 rows][64 k] fp16. chunk = pair*5+kc.
// row d = blk_l*48 + slot; j = pair*128 + blk_l*16 + (slot%16);
// slot/16: 0=z,1=r,2=hh(kc<4)/xh(kc==4). k = kc*64+kk (kc<4: Rw; kc==4: Kw[1+kk]).
// blk_l == wn: each wn warp-pair consumes rows [wn*48, wn*48+48).
__device__ __align__(256) __half g_W[10 * 384 * 64];
__device__ __align__(256) __half g_f16[(size_t)BB * TT * FF];  // features fp16
__device__ float g_epi[HH * 8];  // {k0z,k0r,k0h,bz,br,bxh,bhh,dw}

// ---------------- helpers ----------------
static __device__ __forceinline__ uint32_t smem_u32(const void* p) {
    uint32_t a;
    asm("{ .reg .u64 t; cvta.to.shared.u64 t, %1; cvt.u32.u64 %0, t; }"
        : "=r"(a) : "l"(p));
    return a;
}
static __device__ __forceinline__ void cpasync16(uint32_t dst, const void* src) {
    asm volatile("cp.async.cg.shared.global [%0], [%1], 16;"
                 :: "r"(dst), "l"(src) : "memory");
}
static __device__ __forceinline__ void ldm4(uint32_t* d, uint32_t a) {
    asm volatile("ldmatrix.sync.aligned.m8n8.x4.shared.b16 {%0,%1,%2,%3}, [%4];"
                 : "=r"(d[0]), "=r"(d[1]), "=r"(d[2]), "=r"(d[3]) : "r"(a));
}
static __device__ __forceinline__ void mmaf16(float* c, const uint32_t* a,
                                              uint32_t b0, uint32_t b1) {
    asm volatile(
        "mma.sync.aligned.m16n8k16.row.col.f32.f16.f16.f32 "
        "{%0,%1,%2,%3},{%4,%5,%6,%7},{%8,%9},{%0,%1,%2,%3};"
        : "+f"(c[0]), "+f"(c[1]), "+f"(c[2]), "+f"(c[3])
        : "r"(a[0]), "r"(a[1]), "r"(a[2]), "r"(a[3]), "r"(b0), "r"(b1));
}
static __device__ __forceinline__ float tanha(float x) {
    float y;
    asm("tanh.approx.f32 %0, %1;" : "=f"(y) : "f"(x));
    return y;
}
// sigmoid via MUFU.TANH: 1 MUFU instead of 2
__device__ __forceinline__ float sigf(float x) {
    return fmaf(tanha(0.5f * x), 0.5f, 0.5f);
}
// accurate tanh for the candidate (protects error budget)
__device__ __forceinline__ float tanhfast(float x) {
    return 1.0f - __fdividef(2.0f, __expf(2.0f * x) + 1.0f);
}
__device__ __forceinline__ float hfpart(uint32_t w, int hi) {
    __half_raw r;
    r.x = hi ? (unsigned short)(w >> 16) : (unsigned short)(w & 0xffff);
    return __half2float(__half(r));
}

// ---------------- prep kernels ----------------
__global__ void prep_feat(const float* __restrict__ f) {
    size_t i = (size_t)blockIdx.x * 256 + threadIdx.x;
    if (i >= (size_t)BB * TT * FF) return;
    g_f16[i] = __float2half_rn(f[i]);
}

__global__ void prep_W(const float* __restrict__ Kw, const float* __restrict__ Rw) {
    int idx = blockIdx.x * 256 + threadIdx.x;
    if (idx >= 10 * 384 * 64) return;
    int kk = idx & 63;
    int d = (idx >> 6) % 384;
    int c10 = idx / (384 * 64);
    int pair = c10 / 5, kc = c10 % 5;
    int blk_l = d / 48, slot = d % 48;
    int gate = slot >> 4, jl = slot & 15;
    int j = pair * 128 + blk_l * 16 + jl;
    int off = (gate == 0) ? 0 : (gate == 1) ? 256 : 512;
    float v;
    if (kc < 4) v = Rw[(kc * 64 + kk) * 768 + off + j];
    else        v = Kw[(1 + kk) * 768 + off + j];
    g_W[idx] = __float2half_rn(v);
}

__global__ void prep_epi(const float* __restrict__ Kw, const float* __restrict__ ib,
                         const float* __restrict__ rb, const float* __restrict__ dw) {
    int j = threadIdx.x;
    float* e = &g_epi[j * 8];
    e[0] = Kw[j];
    e[1] = Kw[256 + j];
    e[2] = Kw[512 + j];
    e[3] = ib[j] + rb[j];
    e[4] = ib[256 + j] + rb[256 + j];
    e[5] = ib[512 + j];
    e[6] = rb[512 + j];
    e[7] = dw[j];
}

// ---------------- persistent scan kernel ----------------
// SMEM: ring 2 slots x [8 wn-pairs x 6KB] = 96K | Apanels 2x5x8K | h_lo 64x264 halfs
//       | epi 8K | prev 2x64f | dacc 64f
#define RING_OFF 0
#define APAN_OFF 98304
#define LO_OFF   180224
#define LOSTRIDE 264
#define EPI_OFF  214016
#define PREV_OFF 222208
#define DACC_OFF 222720
#define SMEM_TOTAL 222976

__global__ __launch_bounds__(512, 1) void scan_kernel(
    const float* __restrict__ hs0, const float* __restrict__ inp0,
    const float* __restrict__ db, float* __restrict__ out) {
    extern __shared__ char sm[];
    const uint32_t smb = smem_u32(sm);
    float* s_epi = (float*)(sm + EPI_OFF);
    float* s_prev = (float*)(sm + PREV_OFF);   // [2][64]
    float* s_dacc = (float*)(sm + DACC_OFF);   // [64]
    __half* s_lo = (__half*)(sm + LO_OFF);     // [64][LOSTRIDE]

    const int tid = threadIdx.x, lane = tid & 31, wid = tid >> 5;
    const int b0 = blockIdx.x * 64;
    const int wm = wid >> 3, wn = wid & 7;     // 2m x 8n warps; warp = 32m x 48n
    const int tq = lane & 3, tr = lane >> 2;

    const int arow = wm * 32 + (lane & 15), asel = lane >> 4;
    const int bsub = lane >> 3, bl8 = lane & 7;
    const int brow0 = ((bsub >> 1) << 3) + bl8, bsel = bsub & 1;  // LOCAL to pair tile

    // ---- precomputed invariant swizzle+row tables (q -> byte offset) ----
    uint32_t aswz[4], bswz[4];
#pragma unroll
    for (int q = 0; q < 4; q++) {
        aswz[q] = (uint32_t)(arow * 128) + (uint32_t)((((q * 2 + asel) ^ (arow & 7)) << 4));
        bswz[q] = (uint32_t)(brow0 * 128) + (uint32_t)((((q * 2 + bsel) ^ (brow0 & 7)) << 4));
    }

    // ---- weight-loader invariants: one src pointer (stepped per chunk) and
    //      precomputed dst bases per ring slot; i advances rows by 4. ----
    const int lr0 = wm * 24 + (lane >> 3);
    const int lcc = lane & 7;
    const __half* wptr = g_W + (size_t)wn * 48 * 64 + (size_t)lr0 * 64 + lcc * 8;
    const uint32_t swzA = (uint32_t)((lcc ^ (lr0 & 7)) << 4);
    const uint32_t swzB = (uint32_t)((lcc ^ ((lr0 + 4) & 7)) << 4);
    const uint32_t pb0 = smb + RING_OFF + wn * 6144u;
    const uint32_t d0_0 = pb0 + (uint32_t)lr0 * 128 + swzA;
    const uint32_t d1_0 = pb0 + (uint32_t)(lr0 + 4) * 128 + swzB;
    const uint32_t d0_1 = d0_0 + 49152u, d1_1 = d1_0 + 49152u;

    // ---- per-pair weight loader; feat(t+1) piggybacks on chunk c%10==8 ----
    auto issue = [&](int c) {
        if (c >= TT * 10) return;
        const int cm = c % 10;
        const int s = c & 1;
        const uint32_t dd0 = s ? d0_1 : d0_0;
        const uint32_t dd1 = s ? d1_1 : d1_0;
#pragma unroll
        for (int i = 0; i < 6; i++) {
            uint32_t dst = ((i & 1) ? dd1 : dd0) + (uint32_t)(i >> 1) * 1024u;
            cpasync16(dst, wptr + i * 256);   // +4 rows = +256 halfs per i
        }
        if (cm == 8) {
            int tn = c / 10 + 1;
            if (tn < TT) {
                int r = tid >> 3, cc = tid & 7;
                uint32_t fb = smb + APAN_OFF + (uint32_t)(tn & 1) * 40960u + 4u * 8192u;
                cpasync16(fb + r * 128 + ((cc ^ (r & 7)) << 4),
                          &g_f16[((size_t)(b0 + r) * TT + tn) * FF + cc * 8]);
            }
        }
        asm volatile("cp.async.commit_group;" ::: "memory");
        wptr += 384 * 64;
        if (cm == 9) wptr -= 10 * 384 * 64;
    };

    issue(0);

    // ---- init: h -> panels[0] + lo ; feat(0) ; epi ; prev ----
    for (int idx = tid; idx < 64 * 256; idx += 512) {
        int m = idx >> 8, j = idx & 255;
        float v = hs0[(size_t)(b0 + m) * HH + j];
        __half hi = __float2half_rn(v);
        s_lo[m * LOSTRIDE + j] = __float2half_rn(v - __half2float(hi));
        int cc = (j & 63) >> 3;
        *(__half*)(sm + APAN_OFF + (j >> 6) * 8192 + m * 128 +
                   ((cc ^ (m & 7)) << 4) + (j & 7) * 2) = hi;
    }
    {   // feat t=0
        int r = tid >> 3, cc = tid & 7;
        *(uint4*)(sm + APAN_OFF + 4 * 8192 + r * 128 + ((cc ^ (r & 7)) << 4)) =
            *(const uint4*)&g_f16[((size_t)(b0 + r) * TT) * FF + cc * 8];
    }
    for (int i = tid; i < 2048; i += 512) s_epi[i] = g_epi[i];
    if (tid < 64) {
        s_prev[tid] = inp0[b0 + tid];
        s_dacc[tid] = 0.f;
    }
    __syncthreads();

    float acc[2][6][4], accx[2][2][4];
#pragma unroll
    for (int mi = 0; mi < 2; mi++) {
#pragma unroll
        for (int a = 0; a < 6; a++)
#pragma unroll
            for (int q = 0; q < 4; q++) acc[mi][a][q] = 0.f;
#pragma unroll
        for (int a = 0; a < 2; a++)
#pragma unroll
            for (int q = 0; q < 4; q++) accx[mi][a][q] = 0.f;
    }

#pragma unroll 1
    for (int c = 0; c < TT * 10; ++c) {
        // Drain own group; 64-thread pair barrier publishes the pair's B tile
        // and proves slot (c+1)&1 is recyclable.
        asm volatile("cp.async.wait_group 0;" ::: "memory");
        asm volatile("bar.sync %0, 64;" :: "r"(1 + wn) : "memory");
        issue(c + 1);

        const int t = c / 10, cm = c % 10, pair = cm / 5, kc = cm % 5;
        const int p = t & 1;
        const uint32_t bb0 = smb + RING_OFF + (uint32_t)(c & 1) * 49152u + wn * 6144u;
        const uint32_t ab0 = smb + APAN_OFF + (uint32_t)p * 40960u + kc * 8192u;
        const bool isx = (kc == 4);

        // Software-pipelined fragment schedule: front-load afr + pp0/pp1 B
        // fragments, then interleave the pp2 load between mma groups so every
        // LDSM has independent work before its first consumer (asm volatile
        // pins program order, so source order IS the schedule).
#pragma unroll
        for (int q = 0; q < 4; q++) {
            uint32_t afr[2][4], va[4], vb[4];
            ldm4(afr[0], ab0 + aswz[q]);
            ldm4(afr[1], ab0 + 2048u + aswz[q]);
            ldm4(va, bb0 + bswz[q]);                 // pp0
            ldm4(vb, bb0 + 2048u + bswz[q]);         // pp1
            // pp0 -> acc[.][0,1]
            mmaf16(acc[0][0], afr[0], va[0], va[1]);
            mmaf16(acc[0][1], afr[0], va[2], va[3]);
            mmaf16(acc[1][0], afr[1], va[0], va[1]);
            mmaf16(acc[1][1], afr[1], va[2], va[3]);
            ldm4(va, bb0 + 4096u + bswz[q]);         // pp2 (reuse va regs)
            // pp1 -> acc[.][2,3]
            mmaf16(acc[0][2], afr[0], vb[0], vb[1]);
            mmaf16(acc[0][3], afr[0], vb[2], vb[3]);
            mmaf16(acc[1][2], afr[1], vb[0], vb[1]);
            mmaf16(acc[1][3], afr[1], vb[2], vb[3]);
            // pp2 -> acc[.][4,5] (hh) or accx (xh on feature chunk)
            if (!isx) {
                mmaf16(acc[0][4], afr[0], va[0], va[1]);
                mmaf16(acc[0][5], afr[0], va[2], va[3]);
                mmaf16(acc[1][4], afr[1], va[0], va[1]);
                mmaf16(acc[1][5], afr[1], va[2], va[3]);
            } else {
                mmaf16(accx[0][0], afr[0], va[0], va[1]);
                mmaf16(accx[0][1], afr[0], va[2], va[3]);
                mmaf16(accx[1][0], afr[1], va[0], va[1]);
                mmaf16(accx[1][1], afr[1], va[2], va[3]);
            }
        }

        if (isx) {
            // ---- fused epilogue for this pair ----
            const int jbase = pair * 128 + wn * 16;
            const uint32_t hrd = APAN_OFF + (uint32_t)p * 40960u;        // byte offs
            const uint32_t hwr = APAN_OFF + (uint32_t)(p ^ 1) * 40960u;  // byte offs

            // hoisted per-o constants: epilogue coeffs + swizzle bases
            float ev[2][2][8];
            uint32_t swzo[2];
            int j0o[2];
#pragma unroll
            for (int o = 0; o < 2; o++) {
                const int j0 = jbase + o * 8 + 2 * tq;
                j0o[o] = j0;
                const int cc = (j0 & 63) >> 3;
                swzo[o] = (uint32_t)((j0 >> 6) * 8192 + ((cc ^ tr) << 4) + (j0 & 7) * 2);
#pragma unroll
                for (int i = 0; i < 2; i++) {
                    const float* e = &s_epi[(j0 + i) * 8];
                    float4 u0 = *(const float4*)e;
                    float4 u1 = *(const float4*)(e + 4);
                    ev[o][i][0] = u0.x; ev[o][i][1] = u0.y;
                    ev[o][i][2] = u0.z; ev[o][i][3] = u0.w;
                    ev[o][i][4] = u1.x; ev[o][i][5] = u1.y;
                    ev[o][i][6] = u1.z; ev[o][i][7] = u1.w;
                }
            }

#pragma unroll
            for (int mi = 0; mi < 2; mi++)
#pragma unroll
                for (int rs = 0; rs < 2; rs++) {
                    const int m = wm * 32 + mi * 16 + rs * 8 + tr;
                    const uint32_t m128 = (uint32_t)m * 128u;
                    const float prev = s_prev[p * 64 + m];
                    float dacc = 0.f;
#pragma unroll
                    for (int o = 0; o < 2; o++) {
                        const int j0 = j0o[o];
                        const uint32_t hoff = swzo[o] + m128;
                        uint32_t hw = *(const uint32_t*)(sm + hrd + hoff);
                        uint32_t lw = *(const uint32_t*)&s_lo[m * LOSTRIDE + j0];
                        float hn2[2];
#pragma unroll
                        for (int i = 0; i < 2; i++) {
                            const float* e = ev[o][i];
                            float cz = acc[mi][0 + o][rs * 2 + i] + prev * e[0] + e[3];
                            float cr = acc[mi][2 + o][rs * 2 + i] + prev * e[1] + e[4];
                            float cx = accx[mi][o][rs * 2 + i] + prev * e[2] + e[5];
                            float ch = acc[mi][4 + o][rs * 2 + i] + e[6];
                            float z = sigf(cz), r = sigf(cr);
                            float cand = tanhfast(cx + r * ch);
                            float hold = hfpart(hw, i) + hfpart(lw, i);
                            float hn = z * hold + (1.f - z) * cand;
                            dacc += hn * e[7];
                            hn2[i] = hn;
                        }
                        __half h0 = __float2half_rn(hn2[0]);
                        __half h1 = __float2half_rn(hn2[1]);
                        __half l0 = __float2half_rn(hn2[0] - __half2float(h0));
                        __half l1 = __float2half_rn(hn2[1] - __half2float(h1));
                        *(uint32_t*)(sm + hwr + hoff) =
                            (uint32_t)__half_as_ushort(h0) |
                            ((uint32_t)__half_as_ushort(h1) << 16);
                        *(uint32_t*)&s_lo[m * LOSTRIDE + j0] =
                            (uint32_t)__half_as_ushort(l0) |
                            ((uint32_t)__half_as_ushort(l1) << 16);
                    }
                    dacc += __shfl_xor_sync(0xffffffffu, dacc, 1);
                    dacc += __shfl_xor_sync(0xffffffffu, dacc, 2);
                    if (tq == 0) atomicAdd(&s_dacc[m], dacc);
                }
            // reset accumulators for the next pair
#pragma unroll
            for (int mi = 0; mi < 2; mi++) {
#pragma unroll
                for (int a = 0; a < 6; a++)
#pragma unroll
                    for (int q = 0; q < 4; q++) acc[mi][a][q] = 0.f;
#pragma unroll
                for (int a = 0; a < 2; a++)
#pragma unroll
                    for (int q = 0; q < 4; q++) accx[mi][a][q] = 0.f;
            }
        }

        if (cm == 9) {
            // CTA barrier #1: all epilogue writes + dacc atomics done.
            __syncthreads();
            if (tid < 64) {
                float v = s_dacc[tid] + db[0];
                s_prev[((t + 1) & 1) * 64 + tid] = v;
                out[(size_t)(b0 + tid) * TT + t] = v;
                s_dacc[tid] = 0.f;
            }
            // CTA barrier #2: publish prev/dacc before step t+1 consumes them.
            __syncthreads();
        }
    }
}

// ---------------- launch ----------------
extern "C" void kernel_launch(void* const* d_in, const int* in_sizes, int n_in,
                              void* d_out, int out_size) {
    const float* feat  = (const float*)d_in[0];
    const float* hs0   = (const float*)d_in[1];
    const float* inp0  = (const float*)d_in[2];
    const float* Kw    = (const float*)d_in[3];
    const float* Rw    = (const float*)d_in[4];
    const float* ibias = (const float*)d_in[5];
    const float* rbias = (const float*)d_in[6];
    const float* dw    = (const float*)d_in[7];
    const float* db    = (const float*)d_in[8];
    float* out = (float*)d_out;

    cudaFuncSetAttribute(scan_kernel, cudaFuncAttributeMaxDynamicSharedMemorySize,
                         SMEM_TOTAL);

    size_t nf = (size_t)BB * TT * FF;
    prep_feat<<<(unsigned)((nf + 255) / 256), 256>>>(feat);
    prep_W<<<(10 * 384 * 64 + 255) / 256, 256>>>(Kw, Rw);
    prep_epi<<<1, 256>>>(Kw, ibias, rbias, dw);

    scan_kernel<<<128, 512, SMEM_TOTAL>>>(hs0, inp0, db, out);
}